// round 2
// baseline (speedup 1.0000x reference)
#include <cuda_runtime.h>
#include <cuda_bf16.h>
#include <math.h>

// Problem constants (fixed by the dataset)
#define B_DIM 8
#define H_DIM 32
#define KVH_DIM 8
#define GROUPS 4          // H/KVH
#define D_DIM 128
#define PAGE_SIZE 16
#define PAGES_PER_SEQ 512
#define L_MAX 4096

#define NWARPS 16
#define NTHREADS (NWARPS * 32)
#define UNROLL 4

// paged_kv_cache strides in floats: (page, kv, head, pos, d)
//  page: 2*8*16*128 = 32768, kv: 16384, head: 2048, pos: 128
#define PAGE_STRIDE 32768
#define KV_STRIDE   16384
#define HEAD_STRIDE 2048

__global__ __launch_bounds__(NTHREADS, 1)
void sparse_paged_attn_kernel(
    const float* __restrict__ q,             // (B,H,1,D)
    const float* __restrict__ kv,            // (total_pages,2,KVH,PS,D)
    const int*   __restrict__ indptr,        // (B+1)
    const int*   __restrict__ page_indices,  // (total_pages)
    const int*   __restrict__ sparse_ind,    // (B,H,L_MAX)
    const int*   __restrict__ sparse_nnz,    // (B,H)
    float*       __restrict__ out)           // (B,H,1,D)
{
    const int bh   = blockIdx.x;          // b*H + h
    const int b    = bh >> 5;             // H=32
    const int h    = bh & 31;
    const int kvh  = h >> 2;              // groups = 4
    const int tid  = threadIdx.x;
    const int wid  = tid >> 5;
    const int lane = tid & 31;

    __shared__ int   s_pages[PAGES_PER_SEQ];
    __shared__ int   s_ind[L_MAX];
    __shared__ float s_m[NWARPS];
    __shared__ float s_s[NWARPS];
    __shared__ float s_acc[NWARPS][D_DIM];

    const int nnz = sparse_nnz[bh];

    // Stage page-table segment for this batch (512 ints)
    {
        const int p0 = indptr[b];
        #pragma unroll
        for (int i = tid; i < PAGES_PER_SEQ; i += NTHREADS)
            s_pages[i] = page_indices[p0 + i];
    }
    // Stage the sparse index row (only the live prefix)
    {
        const int* ind_row = sparse_ind + (size_t)bh * L_MAX;
        for (int i = tid; i < nnz; i += NTHREADS)
            s_ind[i] = ind_row[i];
    }

    // q fragment: lane owns d = [lane*4, lane*4+4)
    float4 q4;
    {
        const float4* qv = (const float4*)(q + (size_t)bh * D_DIM);
        q4 = qv[lane];
    }
    __syncthreads();

    const float scale = 0.08838834764831845f;  // 1/sqrt(128)

    float  m    = -1e30f;
    float  ssum = 0.0f;
    float4 acc  = make_float4(0.f, 0.f, 0.f, 0.f);

    // Each warp processes UNROLL consecutive indices per step, warps strided.
    for (int base = wid * UNROLL; base < nnz; base += NWARPS * UNROLL) {
        float4 kk[UNROLL], vv[UNROLL];

        // Issue all K and V loads up-front (8 LDG.128 in flight per warp)
        #pragma unroll
        for (int u = 0; u < UNROLL; u++) {
            const int  l     = base + u;
            const bool valid = (l < nnz);
            const int  i     = valid ? s_ind[l] : 0;
            const int  page  = s_pages[i >> 4];
            const size_t off = ((size_t)page << 15)
                             + ((size_t)kvh << 11)
                             + ((size_t)(i & 15) << 7)
                             + (size_t)(lane << 2);
            if (valid) {
                kk[u] = *(const float4*)(kv + off);
                vv[u] = *(const float4*)(kv + off + KV_STRIDE);
            } else {
                kk[u] = make_float4(0.f, 0.f, 0.f, 0.f);
                vv[u] = kk[u];
            }
        }

        // Dot products + butterfly reduce (all lanes get the score)
        float sc[UNROLL];
        #pragma unroll
        for (int u = 0; u < UNROLL; u++) {
            float d = kk[u].x * q4.x + kk[u].y * q4.y
                    + kk[u].z * q4.z + kk[u].w * q4.w;
            #pragma unroll
            for (int o = 16; o > 0; o >>= 1)
                d += __shfl_xor_sync(0xffffffffu, d, o);
            sc[u] = (base + u < nnz) ? d * scale : -1e30f;
        }

        // Online softmax update across the UNROLL group
        float mnew = m;
        #pragma unroll
        for (int u = 0; u < UNROLL; u++) mnew = fmaxf(mnew, sc[u]);

        const float alpha = __expf(m - mnew);
        float p[UNROLL];
        float psum = 0.0f;
        #pragma unroll
        for (int u = 0; u < UNROLL; u++) {
            p[u] = __expf(sc[u] - mnew);
            psum += p[u];
        }

        acc.x *= alpha; acc.y *= alpha; acc.z *= alpha; acc.w *= alpha;
        #pragma unroll
        for (int u = 0; u < UNROLL; u++) {
            acc.x += p[u] * vv[u].x;
            acc.y += p[u] * vv[u].y;
            acc.z += p[u] * vv[u].z;
            acc.w += p[u] * vv[u].w;
        }
        ssum = ssum * alpha + psum;
        m    = mnew;
    }

    // Publish per-warp partials
    s_acc[wid][lane * 4 + 0] = acc.x;
    s_acc[wid][lane * 4 + 1] = acc.y;
    s_acc[wid][lane * 4 + 2] = acc.z;
    s_acc[wid][lane * 4 + 3] = acc.w;
    if (lane == 0) { s_m[wid] = m; s_s[wid] = ssum; }
    __syncthreads();

    // Cross-warp log-sum-exp merge; 128 threads, one per output dim
    if (tid < D_DIM) {
        float M = -1e30f;
        #pragma unroll
        for (int w = 0; w < NWARPS; w++) M = fmaxf(M, s_m[w]);
        float denom = 0.f, num = 0.f;
        #pragma unroll
        for (int w = 0; w < NWARPS; w++) {
            const float c = __expf(s_m[w] - M);
            denom += c * s_s[w];
            num   += c * s_acc[w][tid];
        }
        out[(size_t)bh * D_DIM + tid] = num / denom;
    }
}

extern "C" void kernel_launch(void* const* d_in, const int* in_sizes, int n_in,
                              void* d_out, int out_size) {
    const float* q            = (const float*)d_in[0];
    const float* kv           = (const float*)d_in[1];
    const int*   indptr       = (const int*)d_in[2];
    const int*   page_indices = (const int*)d_in[3];
    const int*   sparse_ind   = (const int*)d_in[4];
    const int*   sparse_nnz   = (const int*)d_in[5];
    float*       out          = (float*)d_out;

    dim3 grid(B_DIM * H_DIM);
    dim3 block(NTHREADS);
    sparse_paged_attn_kernel<<<grid, block>>>(
        q, kv, indptr, page_indices, sparse_ind, sparse_nnz, out);
}

// round 3
// speedup vs baseline: 1.7094x; 1.7094x over previous
#include <cuda_runtime.h>
#include <cuda_bf16.h>
#include <math.h>

// Problem constants (fixed by the dataset)
#define B_DIM 8
#define H_DIM 32
#define D_DIM 128
#define PAGE_SIZE 16
#define PAGES_PER_SEQ 512
#define L_MAX 4096

#define SPLIT 4                 // chunks per (b,h)
#define NWARPS 8
#define NTHREADS (NWARPS * 32)
#define UNROLL 4
#define CHUNK_MAX ((L_MAX + SPLIT - 1) / SPLIT)   // 1024

#define KV_STRIDE 16384         // floats between K and V of same page/head

// Split-K scratch: per (bh, split) partial softmax state
__device__ float g_m[B_DIM * H_DIM * SPLIT];
__device__ float g_s[B_DIM * H_DIM * SPLIT];
__device__ float g_acc[B_DIM * H_DIM * SPLIT * D_DIM];

__global__ __launch_bounds__(NTHREADS, 4)
void sparse_attn_partial_kernel(
    const float* __restrict__ q,             // (B,H,1,D)
    const float* __restrict__ kv,            // (total_pages,2,KVH,PS,D)
    const int*   __restrict__ indptr,        // (B+1)
    const int*   __restrict__ page_indices,  // (total_pages)
    const int*   __restrict__ sparse_ind,    // (B,H,L_MAX)
    const int*   __restrict__ sparse_nnz)    // (B,H)
{
    const int blk  = blockIdx.x;
    const int bh   = blk >> 2;            // / SPLIT
    const int sp   = blk & (SPLIT - 1);
    const int b    = bh >> 5;             // H=32
    const int h    = bh & 31;
    const int kvh  = h >> 2;              // groups=4
    const int tid  = threadIdx.x;
    const int wid  = tid >> 5;
    const int lane = tid & 31;

    __shared__ int   s_pages[PAGES_PER_SEQ];
    __shared__ int   s_ind[CHUNK_MAX];
    __shared__ float s_m[NWARPS];
    __shared__ float s_s[NWARPS];
    __shared__ float s_acc[NWARPS][D_DIM];

    const int nnz   = sparse_nnz[bh];
    const int chunk = (nnz + SPLIT - 1) >> 2;     // ceil(nnz/SPLIT)
    const int start = sp * chunk;
    const int end   = min(start + chunk, nnz);
    const int cnt   = end - start;                // may be <= 0

    // Stage page-table segment for this batch (512 ints)
    {
        const int p0 = indptr[b];
        #pragma unroll
        for (int i = tid; i < PAGES_PER_SEQ; i += NTHREADS)
            s_pages[i] = page_indices[p0 + i];
    }
    // Stage this chunk of the sparse index row
    {
        const int* ind_row = sparse_ind + (size_t)bh * L_MAX + start;
        for (int i = tid; i < cnt; i += NTHREADS)
            s_ind[i] = ind_row[i];
    }

    // q fragment: lane owns d = [lane*4, lane*4+4)
    float4 q4 = ((const float4*)(q + (size_t)bh * D_DIM))[lane];
    __syncthreads();

    const float scale = 0.08838834764831845f;  // 1/sqrt(128)

    float  m    = -1e30f;
    float  ssum = 0.0f;
    float4 acc  = make_float4(0.f, 0.f, 0.f, 0.f);

    for (int base = wid * UNROLL; base < cnt; base += NWARPS * UNROLL) {
        float4 kk[UNROLL], vv[UNROLL];

        // Issue all K and V loads up-front (8 LDG.128 in flight per warp)
        #pragma unroll
        for (int u = 0; u < UNROLL; u++) {
            const int  l     = base + u;
            const bool valid = (l < cnt);
            const int  i     = valid ? s_ind[l] : 0;
            const int  page  = s_pages[i >> 4];
            const size_t off = ((size_t)page << 15)
                             + ((size_t)kvh << 11)
                             + ((size_t)(i & 15) << 7)
                             + (size_t)(lane << 2);
            if (valid) {
                kk[u] = *(const float4*)(kv + off);
                vv[u] = *(const float4*)(kv + off + KV_STRIDE);
            } else {
                kk[u] = make_float4(0.f, 0.f, 0.f, 0.f);
                vv[u] = kk[u];
            }
        }

        // Dot products + butterfly reduce (all lanes get the score)
        float sc[UNROLL];
        #pragma unroll
        for (int u = 0; u < UNROLL; u++) {
            float d = kk[u].x * q4.x + kk[u].y * q4.y
                    + kk[u].z * q4.z + kk[u].w * q4.w;
            #pragma unroll
            for (int o = 16; o > 0; o >>= 1)
                d += __shfl_xor_sync(0xffffffffu, d, o);
            sc[u] = (base + u < cnt) ? d * scale : -1e30f;
        }

        // Online softmax update across the UNROLL group
        float mnew = m;
        #pragma unroll
        for (int u = 0; u < UNROLL; u++) mnew = fmaxf(mnew, sc[u]);

        const float alpha = __expf(m - mnew);
        float p[UNROLL];
        float psum = 0.0f;
        #pragma unroll
        for (int u = 0; u < UNROLL; u++) {
            p[u] = __expf(sc[u] - mnew);
            psum += p[u];
        }

        acc.x *= alpha; acc.y *= alpha; acc.z *= alpha; acc.w *= alpha;
        #pragma unroll
        for (int u = 0; u < UNROLL; u++) {
            acc.x += p[u] * vv[u].x;
            acc.y += p[u] * vv[u].y;
            acc.z += p[u] * vv[u].z;
            acc.w += p[u] * vv[u].w;
        }
        ssum = ssum * alpha + psum;
        m    = mnew;
    }

    // Publish per-warp partials
    s_acc[wid][lane * 4 + 0] = acc.x;
    s_acc[wid][lane * 4 + 1] = acc.y;
    s_acc[wid][lane * 4 + 2] = acc.z;
    s_acc[wid][lane * 4 + 3] = acc.w;
    if (lane == 0) { s_m[wid] = m; s_s[wid] = ssum; }
    __syncthreads();

    // Cross-warp merge -> global split-K partial (threads 0..127, one per d)
    if (tid < D_DIM) {
        float M = -1e30f;
        #pragma unroll
        for (int w = 0; w < NWARPS; w++) M = fmaxf(M, s_m[w]);
        float denom = 0.f, num = 0.f;
        #pragma unroll
        for (int w = 0; w < NWARPS; w++) {
            const float c = __expf(s_m[w] - M);
            denom += c * s_s[w];
            num   += c * s_acc[w][tid];
        }
        g_acc[(size_t)blk * D_DIM + tid] = num;
        if (tid == 0) { g_m[blk] = M; g_s[blk] = denom; }
    }
}

// Merge SPLIT partials per (b,h) with log-sum-exp
__global__ __launch_bounds__(D_DIM)
void sparse_attn_merge_kernel(float* __restrict__ out)
{
    const int bh = blockIdx.x;
    const int d  = threadIdx.x;

    float M = -1e30f;
    #pragma unroll
    for (int s = 0; s < SPLIT; s++) M = fmaxf(M, g_m[bh * SPLIT + s]);

    float denom = 0.f, num = 0.f;
    #pragma unroll
    for (int s = 0; s < SPLIT; s++) {
        const float c = __expf(g_m[bh * SPLIT + s] - M);
        denom += c * g_s[bh * SPLIT + s];
        num   += c * g_acc[(size_t)(bh * SPLIT + s) * D_DIM + d];
    }
    out[(size_t)bh * D_DIM + d] = num / denom;
}

extern "C" void kernel_launch(void* const* d_in, const int* in_sizes, int n_in,
                              void* d_out, int out_size) {
    const float* q            = (const float*)d_in[0];
    const float* kv           = (const float*)d_in[1];
    const int*   indptr       = (const int*)d_in[2];
    const int*   page_indices = (const int*)d_in[3];
    const int*   sparse_ind   = (const int*)d_in[4];
    const int*   sparse_nnz   = (const int*)d_in[5];
    float*       out          = (float*)d_out;

    sparse_attn_partial_kernel<<<B_DIM * H_DIM * SPLIT, NTHREADS>>>(
        q, kv, indptr, page_indices, sparse_ind, sparse_nnz);
    sparse_attn_merge_kernel<<<B_DIM * H_DIM, D_DIM>>>(out);
}

// round 6
// speedup vs baseline: 1.8038x; 1.0552x over previous
#include <cuda_runtime.h>
#include <cuda_bf16.h>
#include <math.h>

// Problem constants (fixed by the dataset)
#define B_DIM 8
#define H_DIM 32
#define D_DIM 128
#define PAGE_SIZE 16
#define PAGES_PER_SEQ 512
#define L_MAX 4096

#define SPLIT 16                // chunks per (b,h)
#define NWARPS 4
#define NTHREADS (NWARPS * 32)  // 128
#define UNROLL 4
#define CHUNK_MAX ((L_MAX + SPLIT - 1) / SPLIT)   // 256

#define KV_STRIDE 16384u        // floats between K and V of same page/head

// Split-K scratch: per (bh, split) partial softmax state
__device__ float g_m[B_DIM * H_DIM * SPLIT];
__device__ float g_s[B_DIM * H_DIM * SPLIT];
__device__ float g_acc[B_DIM * H_DIM * SPLIT * D_DIM];
__device__ unsigned int g_cnt[B_DIM * H_DIM];   // zero-init; reset after each use

__global__ __launch_bounds__(NTHREADS, 8)
void sparse_attn_kernel(
    const float* __restrict__ q,             // (B,H,1,D)
    const float* __restrict__ kv,            // (total_pages,2,KVH,PS,D)
    const int*   __restrict__ indptr,        // (B+1)
    const int*   __restrict__ page_indices,  // (total_pages)
    const int*   __restrict__ sparse_ind,    // (B,H,L_MAX)
    const int*   __restrict__ sparse_nnz,    // (B,H)
    float*       __restrict__ out)           // (B,H,1,D)
{
    const int blk  = blockIdx.x;
    const int bh   = blk >> 4;            // / SPLIT
    const int sp   = blk & (SPLIT - 1);
    const int b    = bh >> 5;             // H=32
    const int h    = bh & 31;
    const int kvh  = h >> 2;              // groups=4
    const int tid  = threadIdx.x;
    const int wid  = tid >> 5;
    const int lane = tid & 31;

    __shared__ int   s_pages[PAGES_PER_SEQ];
    __shared__ int   s_ind[CHUNK_MAX];
    __shared__ float s_m[NWARPS];
    __shared__ float s_s[NWARPS];
    __shared__ float s_acc[NWARPS][D_DIM];
    __shared__ int   s_is_last;

    const int nnz   = sparse_nnz[bh];
    const int chunk = (nnz + SPLIT - 1) >> 4;     // ceil(nnz/SPLIT)
    const int start = sp * chunk;
    const int end   = min(start + chunk, nnz);
    const int cnt   = end - start;                // may be <= 0

    // Stage page-table segment for this batch (512 ints)
    {
        const int p0 = indptr[b];
        #pragma unroll
        for (int i = tid; i < PAGES_PER_SEQ; i += NTHREADS)
            s_pages[i] = page_indices[p0 + i];
    }
    // Stage this chunk of the sparse index row
    {
        const int* ind_row = sparse_ind + (size_t)bh * L_MAX + start;
        for (int i = tid; i < cnt; i += NTHREADS)
            s_ind[i] = ind_row[i];
    }

    // q fragment: lane owns d = [lane*4, lane*4+4)
    float4 q4 = ((const float4*)(q + (size_t)bh * D_DIM))[lane];
    __syncthreads();

    const float scale = 0.08838834764831845f;  // 1/sqrt(128)

    float  m    = -1e30f;
    float  ssum = 0.0f;
    float4 acc  = make_float4(0.f, 0.f, 0.f, 0.f);

    for (int base = wid * UNROLL; base < cnt; base += NWARPS * UNROLL) {
        float4 kk[UNROLL], vv[UNROLL];

        // Issue all K and V loads up-front (8 LDG.128 in flight per warp)
        #pragma unroll
        for (int u = 0; u < UNROLL; u++) {
            const int  l     = base + u;
            const bool valid = (l < cnt);
            const int  i     = valid ? s_ind[l] : 0;
            const unsigned page = (unsigned)s_pages[i >> 4];
            const unsigned off  = (page << 15)
                                + ((unsigned)kvh << 11)
                                + ((unsigned)(i & 15) << 7)
                                + ((unsigned)lane << 2);
            if (valid) {
                kk[u] = *(const float4*)(kv + off);
                vv[u] = *(const float4*)(kv + off + KV_STRIDE);
            } else {
                kk[u] = make_float4(0.f, 0.f, 0.f, 0.f);
                vv[u] = kk[u];
            }
        }

        // Dot products + butterfly reduce (all lanes get the score)
        float sc[UNROLL];
        #pragma unroll
        for (int u = 0; u < UNROLL; u++) {
            float d = kk[u].x * q4.x + kk[u].y * q4.y
                    + kk[u].z * q4.z + kk[u].w * q4.w;
            #pragma unroll
            for (int o = 16; o > 0; o >>= 1)
                d += __shfl_xor_sync(0xffffffffu, d, o);
            sc[u] = (base + u < cnt) ? d * scale : -1e30f;
        }

        // Online softmax update across the UNROLL group
        float mnew = m;
        #pragma unroll
        for (int u = 0; u < UNROLL; u++) mnew = fmaxf(mnew, sc[u]);

        const float alpha = __expf(m - mnew);
        float p[UNROLL];
        float psum = 0.0f;
        #pragma unroll
        for (int u = 0; u < UNROLL; u++) {
            p[u] = __expf(sc[u] - mnew);
            psum += p[u];
        }

        acc.x *= alpha; acc.y *= alpha; acc.z *= alpha; acc.w *= alpha;
        #pragma unroll
        for (int u = 0; u < UNROLL; u++) {
            acc.x += p[u] * vv[u].x;
            acc.y += p[u] * vv[u].y;
            acc.z += p[u] * vv[u].z;
            acc.w += p[u] * vv[u].w;
        }
        ssum = ssum * alpha + psum;
        m    = mnew;
    }

    // Publish per-warp partials to smem
    s_acc[wid][lane * 4 + 0] = acc.x;
    s_acc[wid][lane * 4 + 1] = acc.y;
    s_acc[wid][lane * 4 + 2] = acc.z;
    s_acc[wid][lane * 4 + 3] = acc.w;
    if (lane == 0) { s_m[wid] = m; s_s[wid] = ssum; }
    __syncthreads();

    // Cross-warp merge -> global split-K partial (128 threads, one per d)
    {
        float M = -1e30f;
        #pragma unroll
        for (int w = 0; w < NWARPS; w++) M = fmaxf(M, s_m[w]);
        float denom = 0.f, num = 0.f;
        #pragma unroll
        for (int w = 0; w < NWARPS; w++) {
            const float c = __expf(s_m[w] - M);
            denom += c * s_s[w];
            num   += c * s_acc[w][tid];
        }
        g_acc[(size_t)blk * D_DIM + tid] = num;
        if (tid == 0) { g_m[blk] = M; g_s[blk] = denom; }
    }

    // Arrival protocol: last block of this bh does the final merge
    __syncthreads();
    if (tid == 0) {
        __threadfence();
        const unsigned old = atomicAdd(&g_cnt[bh], 1u);
        s_is_last = (old == SPLIT - 1);
        if (s_is_last) g_cnt[bh] = 0;   // reset for next graph replay
    }
    __syncthreads();

    if (s_is_last) {
        __threadfence();   // acquire: make other blocks' fenced writes visible
        const int base = bh * SPLIT;
        float M = -1e30f;
        #pragma unroll
        for (int s = 0; s < SPLIT; s++) M = fmaxf(M, g_m[base + s]);
        float denom = 0.f, num = 0.f;
        #pragma unroll
        for (int s = 0; s < SPLIT; s++) {
            const float c = __expf(g_m[base + s] - M);
            denom += c * g_s[base + s];
            num   += c * g_acc[(size_t)(base + s) * D_DIM + tid];
        }
        out[(size_t)bh * D_DIM + tid] = num / denom;
    }
}

extern "C" void kernel_launch(void* const* d_in, const int* in_sizes, int n_in,
                              void* d_out, int out_size) {
    const float* q            = (const float*)d_in[0];
    const float* kv           = (const float*)d_in[1];
    const int*   indptr       = (const int*)d_in[2];
    const int*   page_indices = (const int*)d_in[3];
    const int*   sparse_ind   = (const int*)d_in[4];
    const int*   sparse_nnz   = (const int*)d_in[5];
    float*       out          = (float*)d_out;

    sparse_attn_kernel<<<B_DIM * H_DIM * SPLIT, NTHREADS>>>(
        q, kv, indptr, page_indices, sparse_ind, sparse_nnz, out);
}

// round 9
// speedup vs baseline: 1.9657x; 1.0898x over previous
#include <cuda_runtime.h>
#include <cuda_bf16.h>
#include <math.h>

// Problem constants (fixed by the dataset)
#define B_DIM 8
#define H_DIM 32
#define D_DIM 128
#define PAGE_SIZE 16
#define PAGES_PER_SEQ 512
#define L_MAX 4096

#define SPLIT 16                // chunks per (b,h)
#define NWARPS 4
#define NTHREADS (NWARPS * 32)  // 128
#define GDEPTH 2                // ring slots (groups) per warp
#define GSIZE 4                 // indices per group
#define CHUNK_MAX ((L_MAX + SPLIT - 1) / SPLIT)   // 256

#define KV_STRIDE 16384u        // floats between K and V of same page/head

// Split-K scratch: per (bh, split) partial softmax state
__device__ float g_m[B_DIM * H_DIM * SPLIT];
__device__ float g_s[B_DIM * H_DIM * SPLIT];
__device__ float g_acc[B_DIM * H_DIM * SPLIT * D_DIM];
__device__ unsigned int g_cnt[B_DIM * H_DIM];   // zero-init; reset after use

__device__ __forceinline__ unsigned smem_u32(const void* p) {
    return (unsigned)__cvta_generic_to_shared(p);
}
#define CP16(dst, src) \
    asm volatile("cp.async.cg.shared.global [%0], [%1], 16;" :: "r"(dst), "l"(src))
#define CP16_ZERO(dst, src) \
    asm volatile("cp.async.cg.shared.global [%0], [%1], 16, 0;" :: "r"(dst), "l"(src))
#define CP_COMMIT()  asm volatile("cp.async.commit_group;")
#define CP_WAIT1()   asm volatile("cp.async.wait_group 1;")
#define CP_WAITALL() asm volatile("cp.async.wait_all;")

__global__ __launch_bounds__(NTHREADS, 6)
void sparse_attn_kernel(
    const float* __restrict__ q,             // (B,H,1,D)
    const float* __restrict__ kv,            // (total_pages,2,KVH,PS,D)
    const int*   __restrict__ indptr,        // (B+1)
    const int*   __restrict__ page_indices,  // (total_pages)
    const int*   __restrict__ sparse_ind,    // (B,H,L_MAX)
    const int*   __restrict__ sparse_nnz,    // (B,H)
    float*       __restrict__ out)           // (B,H,1,D)
{
    const int blk  = blockIdx.x;
    const int bh   = blk >> 4;            // / SPLIT
    const int sp   = blk & (SPLIT - 1);
    const int b    = bh >> 5;             // H=32
    const int h    = bh & 31;
    const int kvh  = h >> 2;              // groups=4
    const int tid  = threadIdx.x;
    const int wid  = tid >> 5;
    const int lane = tid & 31;

    __shared__ int   s_pages[PAGES_PER_SEQ];
    __shared__ int   s_ind[CHUNK_MAX];
    // per-warp ring: [warp][slot][K/V][idx-in-group][d]
    __shared__ float s_ring[NWARPS][GDEPTH][2][GSIZE][D_DIM];
    __shared__ float s_m[NWARPS];
    __shared__ float s_s[NWARPS];
    __shared__ float s_acc[NWARPS][D_DIM];
    __shared__ int   s_is_last;

    const int nnz   = sparse_nnz[bh];
    const int chunk = (nnz + SPLIT - 1) >> 4;     // ceil(nnz/SPLIT)
    const int start = sp * chunk;
    const int end   = min(start + chunk, nnz);
    const int cnt   = end - start;                // may be <= 0

    // Stage page-table segment for this batch (512 ints)
    {
        const int p0 = indptr[b];
        #pragma unroll
        for (int i = tid; i < PAGES_PER_SEQ; i += NTHREADS)
            s_pages[i] = page_indices[p0 + i];
    }
    // Stage this chunk of the sparse index row
    {
        const int* ind_row = sparse_ind + (size_t)bh * L_MAX + start;
        for (int i = tid; i < cnt; i += NTHREADS)
            s_ind[i] = ind_row[i];
    }

    // q fragment: lane owns d = [lane*4, lane*4+4)
    float4 q4 = ((const float4*)(q + (size_t)bh * D_DIM))[lane];
    __syncthreads();

    const float scale = 0.08838834764831845f;  // 1/sqrt(128)

    float  m    = -1e30f;
    float  ssum = 0.0f;
    float4 acc  = make_float4(0.f, 0.f, 0.f, 0.f);

    // Warp w owns groups g = w, w+NWARPS, ... ; group g covers l = 4g..4g+3
    const int total_groups = (cnt + GSIZE - 1) >> 2;           // over chunk
    const int n_w = (total_groups > wid)
                  ? (total_groups - wid + NWARPS - 1) / NWARPS : 0;

    // smem dst base for this warp's ring, lane's 16B within a row
    const unsigned ring_base = smem_u32(&s_ring[wid][0][0][0][0]) + lane * 16u;

    // ---- issue one group (t-th local group) into ring slot t&1 ----
    auto issue_group = [&](int t) {
        const int  l0   = (wid + t * NWARPS) * GSIZE;
        const unsigned slot = ring_base + (unsigned)(t & 1) * (2u * GSIZE * D_DIM * 4u);
        #pragma unroll
        for (int u = 0; u < GSIZE; u++) {
            const int  l     = l0 + u;
            const bool valid = (l < cnt);
            const int  i     = valid ? s_ind[l] : 0;
            const unsigned page = (unsigned)s_pages[i >> 4];
            const float* src = kv + ((page << 15)
                                   + ((unsigned)kvh << 11)
                                   + ((unsigned)(i & 15) << 7)
                                   + ((unsigned)lane << 2));
            const unsigned dk = slot + (unsigned)u * (D_DIM * 4u);
            const unsigned dv = dk + (unsigned)(GSIZE * D_DIM * 4u);
            if (valid) {
                CP16(dk, src);
                CP16(dv, src + KV_STRIDE);
            } else {
                CP16_ZERO(dk, src);
                CP16_ZERO(dv, src);
            }
        }
        CP_COMMIT();
    };

    if (n_w > 0) {
        issue_group(0);
        issue_group(1);

        for (int t = 0; t < n_w; t++) {
            CP_WAIT1();          // oldest group (t) complete
            __syncwarp();

            const int  l0   = (wid + t * NWARPS) * GSIZE;
            const int  slot = t & 1;

            // Load K rows, compute scores
            float4 kk[GSIZE];
            #pragma unroll
            for (int u = 0; u < GSIZE; u++)
                kk[u] = *(const float4*)&s_ring[wid][slot][0][u][lane * 4];

            float sc[GSIZE];
            #pragma unroll
            for (int u = 0; u < GSIZE; u++) {
                float d = kk[u].x * q4.x + kk[u].y * q4.y
                        + kk[u].z * q4.z + kk[u].w * q4.w;
                #pragma unroll
                for (int o = 16; o > 0; o >>= 1)
                    d += __shfl_xor_sync(0xffffffffu, d, o);
                sc[u] = (l0 + u < cnt) ? d * scale : -1e30f;
            }

            // Load V rows
            float4 vv[GSIZE];
            #pragma unroll
            for (int u = 0; u < GSIZE; u++)
                vv[u] = *(const float4*)&s_ring[wid][slot][1][u][lane * 4];

            __syncwarp();        // all lanes done reading slot
            issue_group(t + 2);  // refill slot (dummy beyond n_w: zero-fill)

            // Online softmax update
            float mnew = m;
            #pragma unroll
            for (int u = 0; u < GSIZE; u++) mnew = fmaxf(mnew, sc[u]);

            const float alpha = __expf(m - mnew);
            float p[GSIZE];
            float psum = 0.0f;
            #pragma unroll
            for (int u = 0; u < GSIZE; u++) {
                p[u] = __expf(sc[u] - mnew);
                psum += p[u];
            }

            acc.x *= alpha; acc.y *= alpha; acc.z *= alpha; acc.w *= alpha;
            #pragma unroll
            for (int u = 0; u < GSIZE; u++) {
                acc.x += p[u] * vv[u].x;
                acc.y += p[u] * vv[u].y;
                acc.z += p[u] * vv[u].z;
                acc.w += p[u] * vv[u].w;
            }
            ssum = ssum * alpha + psum;
            m    = mnew;
        }
    }
    CP_WAITALL();   // drain any dummy in-flight groups before smem reuse/exit

    // Publish per-warp partials to smem
    s_acc[wid][lane * 4 + 0] = acc.x;
    s_acc[wid][lane * 4 + 1] = acc.y;
    s_acc[wid][lane * 4 + 2] = acc.z;
    s_acc[wid][lane * 4 + 3] = acc.w;
    if (lane == 0) { s_m[wid] = m; s_s[wid] = ssum; }
    __syncthreads();

    // Cross-warp merge -> global split-K partial (128 threads, one per d)
    {
        float M = -1e30f;
        #pragma unroll
        for (int w = 0; w < NWARPS; w++) M = fmaxf(M, s_m[w]);
        float denom = 0.f, num = 0.f;
        #pragma unroll
        for (int w = 0; w < NWARPS; w++) {
            const float c = __expf(s_m[w] - M);
            denom += c * s_s[w];
            num   += c * s_acc[w][tid];
        }
        g_acc[(size_t)blk * D_DIM + tid] = num;
        if (tid == 0) { g_m[blk] = M; g_s[blk] = denom; }
    }

    // Arrival protocol: last block of this bh does the final merge
    __syncthreads();
    if (tid == 0) {
        __threadfence();
        const unsigned old = atomicAdd(&g_cnt[bh], 1u);
        s_is_last = (old == SPLIT - 1);
        if (s_is_last) g_cnt[bh] = 0;   // reset for next graph replay
    }
    __syncthreads();

    if (s_is_last) {
        __threadfence();   // acquire: make other blocks' fenced writes visible
        const int base = bh * SPLIT;
        float M = -1e30f;
        #pragma unroll
        for (int s = 0; s < SPLIT; s++) M = fmaxf(M, g_m[base + s]);
        float denom = 0.f, num = 0.f;
        #pragma unroll
        for (int s = 0; s < SPLIT; s++) {
            const float c = __expf(g_m[base + s] - M);
            denom += c * g_s[base + s];
            num   += c * g_acc[(size_t)(base + s) * D_DIM + tid];
        }
        out[(size_t)bh * D_DIM + tid] = num / denom;
    }
}

extern "C" void kernel_launch(void* const* d_in, const int* in_sizes, int n_in,
                              void* d_out, int out_size) {
    const float* q            = (const float*)d_in[0];
    const float* kv           = (const float*)d_in[1];
    const int*   indptr       = (const int*)d_in[2];
    const int*   page_indices = (const int*)d_in[3];
    const int*   sparse_ind   = (const int*)d_in[4];
    const int*   sparse_nnz   = (const int*)d_in[5];
    float*       out          = (float*)d_out;

    sparse_attn_kernel<<<B_DIM * H_DIM * SPLIT, NTHREADS>>>(
        q, kv, indptr, page_indices, sparse_ind, sparse_nnz, out);
}